// round 5
// baseline (speedup 1.0000x reference)
#include <cuda_runtime.h>
#include <cuda_bf16.h>
#include <math.h>
#include <stdint.h>

// Problem constants
#define PB 2
#define PL 2048
#define PD 768
#define PH 12
#define PDK 64
#define M1 (PB*PL)        // 4096
#define NQKV (3*PD)       // 2304

// ---------------------------------------------------------------------------
// Scratch (__device__ globals; allocation-free rule)
// ---------------------------------------------------------------------------
__device__ float g_Q[PB*PH*PDK*PL];   // [b][h][dk][l]  (transposed)
__device__ float g_K[PB*PH*PDK*PL];   // [b][h][dk][l]
__device__ float g_V[PB*PH*PL*PDK];   // [b][h][l][dk]
__device__ float g_A[PB*PL*PD];       // attention out, [b][l][h*dk]

// bf16 hi/lo splits (16B-aligned for cp.async)
__device__ __align__(256) __nv_bfloat16 g_xh[M1*PD],    g_xl[M1*PD];     // x [M][K]
__device__ __align__(256) __nv_bfloat16 g_Wqh[NQKV*PD], g_Wql[NQKV*PD];  // Wqkv^T [N][K]
__device__ __align__(256) __nv_bfloat16 g_Woh[PD*PD],   g_Wol[PD*PD];    // Wo^T [N][K]
__device__ __align__(256) __nv_bfloat16 g_Ah[M1*PD],    g_Al[M1*PD];     // attn out [M][K]

// ---------------------------------------------------------------------------
// PTX helpers (plain sm_80/90 instructions only -- no 'a'-target features)
// ---------------------------------------------------------------------------
__device__ __forceinline__ uint32_t smem_u32(const void* p) {
    uint32_t a;
    asm("{ .reg .u64 t; cvta.to.shared.u64 t, %1; cvt.u32.u64 %0, t; }" : "=r"(a) : "l"(p));
    return a;
}
__device__ __forceinline__ void cpa16(uint32_t saddr, const void* g) {
    asm volatile("cp.async.cg.shared.global [%0], [%1], 16;\n" :: "r"(saddr), "l"(g));
}
__device__ __forceinline__ void cpa_commit() {
    asm volatile("cp.async.commit_group;\n" ::: "memory");
}
__device__ __forceinline__ void ldm_x4(uint32_t* r, uint32_t addr) {
    asm volatile("ldmatrix.sync.aligned.m8n8.x4.shared.b16 {%0,%1,%2,%3}, [%4];\n"
        : "=r"(r[0]), "=r"(r[1]), "=r"(r[2]), "=r"(r[3]) : "r"(addr));
}
__device__ __forceinline__ void mma_bf16(float* d, const uint32_t* a, const uint32_t* b) {
    asm volatile(
        "mma.sync.aligned.m16n8k16.row.col.f32.bf16.bf16.f32 "
        "{%0,%1,%2,%3}, {%4,%5,%6,%7}, {%8,%9}, {%0,%1,%2,%3};\n"
        : "+f"(d[0]), "+f"(d[1]), "+f"(d[2]), "+f"(d[3])
        : "r"(a[0]), "r"(a[1]), "r"(a[2]), "r"(a[3]), "r"(b[0]), "r"(b[1]));
}

// ---------------------------------------------------------------------------
// Prep kernels: fp32 -> bf16 hi/lo split
// ---------------------------------------------------------------------------
template<bool FROM_GA>
__global__ void split_pair(const float* __restrict__ in_p,
                           __nv_bfloat16* __restrict__ oh,
                           __nv_bfloat16* __restrict__ ol, int n2)
{
    const float* in = FROM_GA ? (const float*)g_A : in_p;
    int i = blockIdx.x * blockDim.x + threadIdx.x;
    if (i < n2) {
        float2 v = ((const float2*)in)[i];
        __nv_bfloat16 hx = __float2bfloat16_rn(v.x);
        __nv_bfloat16 hy = __float2bfloat16_rn(v.y);
        __nv_bfloat162 hv; hv.x = hx; hv.y = hy;
        __nv_bfloat162 lv;
        lv.x = __float2bfloat16_rn(v.x - __bfloat162float(hx));
        lv.y = __float2bfloat16_rn(v.y - __bfloat162float(hy));
        ((__nv_bfloat162*)oh)[i] = hv;
        ((__nv_bfloat162*)ol)[i] = lv;
    }
}

// Transpose+split: in [K][N] fp32 -> oh/ol [N][K] bf16
__global__ void transpose_split(const float* __restrict__ in,
                                __nv_bfloat16* __restrict__ oh,
                                __nv_bfloat16* __restrict__ ol, int K, int N)
{
    __shared__ float t[32][33];
    int n0 = blockIdx.x * 32, k0 = blockIdx.y * 32;
    int tx = threadIdx.x, ty = threadIdx.y;
#pragma unroll
    for (int r = 0; r < 4; ++r)
        t[ty + 8*r][tx] = in[(size_t)(k0 + ty + 8*r) * N + n0 + tx];
    __syncthreads();
#pragma unroll
    for (int r = 0; r < 4; ++r) {
        float v = t[tx][ty + 8*r];
        __nv_bfloat16 h = __float2bfloat16_rn(v);
        size_t o = (size_t)(n0 + ty + 8*r) * K + k0 + tx;
        oh[o] = h;
        ol[o] = __float2bfloat16_rn(v - __bfloat162float(h));
    }
}

// ---------------------------------------------------------------------------
// HMMA (mma.sync) GEMM, bf16 3-pass split: C[M,N] = A[M,K] @ B[N,K]^T + bias
// Tile 128x128x32, 256 threads (8 warps, 4Mx2N), warp tile 32x64.
// Smem: stride-40 bf16 rows (80B) -> conflict-free ldmatrix; double-buffered
// cp.async. MODE 0: scatter to g_Q/g_K (transposed) & g_V.  MODE 1: write C.
// ---------------------------------------------------------------------------
#define MAT_STRIDE 40                 // bf16 elems per row (padded from 32)
#define MAT_BYTES  (128*MAT_STRIDE*2) // 10240
#define OFF_AH 0
#define OFF_AL (MAT_BYTES)
#define OFF_BH (2*MAT_BYTES)
#define OFF_BL (3*MAT_BYTES)
#define STG    (4*MAT_BYTES)          // 40960 per stage
#define TGSMEM (2*STG)                // 81920

template<int MODE>
__global__ __launch_bounds__(256, 1)
void tc_gemm(const __nv_bfloat16* __restrict__ Ahg, const __nv_bfloat16* __restrict__ Alg,
             const __nv_bfloat16* __restrict__ Bhg, const __nv_bfloat16* __restrict__ Blg,
             const float* __restrict__ bias, float* __restrict__ Cout)
{
    extern __shared__ char smem[];
    uint32_t sb = smem_u32(smem);
    int tid  = threadIdx.x;
    int wid  = tid >> 5;
    int lane = tid & 31;
    int m0 = blockIdx.y * 128;
    int n0 = blockIdx.x * 128;
    int wm = wid >> 1;      // 0..3 -> 32-row band
    int wn = wid & 1;       // 0..1 -> 64-col band

    float acc[2][8][4];
#pragma unroll
    for (int mt = 0; mt < 2; ++mt)
#pragma unroll
        for (int nt = 0; nt < 8; ++nt)
#pragma unroll
            for (int q = 0; q < 4; ++q) acc[mt][nt][q] = 0.f;

#define LOAD_STAGE(s, kt) do { \
    uint32_t stb_ = sb + (s) * STG; \
    int kk_ = (kt) * 32; \
    _Pragma("unroll") \
    for (int jj = 0; jj < 2; ++jj) { \
        int id = tid + 256 * jj; \
        int row = id >> 2, c4 = id & 3; \
        uint32_t soff = (uint32_t)(row * (MAT_STRIDE*2) + c4 * 16); \
        size_t ga = (size_t)(m0 + row) * PD + kk_ + c4 * 8; \
        size_t gb = (size_t)(n0 + row) * PD + kk_ + c4 * 8; \
        cpa16(stb_ + OFF_AH + soff, Ahg + ga); \
        cpa16(stb_ + OFF_AL + soff, Alg + ga); \
        cpa16(stb_ + OFF_BH + soff, Bhg + gb); \
        cpa16(stb_ + OFF_BL + soff, Blg + gb); \
    } \
} while (0)

    const int NIT = PD / 32;   // 24
    LOAD_STAGE(0, 0);
    cpa_commit();

    // ldmatrix address components (constant across iterations)
    int rA    = wm * 32 + (lane & 15);            // + mt*16
    int koffA = (lane >> 4) << 3;                 // + ks*16
    int rB    = wn * 64 + ((lane >> 4) << 3) + (lane & 7);  // + ntp*16
    int koffB = ((lane >> 3) & 1) << 3;           // + ks*16

    for (int it = 0; it < NIT; ++it) {
        int s = it & 1;
        if (it + 1 < NIT) {
            LOAD_STAGE(s ^ 1, it + 1);
            cpa_commit();
            asm volatile("cp.async.wait_group 1;\n" ::: "memory");
        } else {
            asm volatile("cp.async.wait_group 0;\n" ::: "memory");
        }
        __syncthreads();

        uint32_t stb = sb + s * STG;
#pragma unroll
        for (int ks = 0; ks < 2; ++ks) {
            uint32_t ah[2][4], al[2][4], bh[4][4], bl[4][4];
#pragma unroll
            for (int mt = 0; mt < 2; ++mt) {
                uint32_t off = (uint32_t)((rA + mt*16) * MAT_STRIDE + koffA + ks*16) * 2;
                ldm_x4(ah[mt], stb + OFF_AH + off);
                ldm_x4(al[mt], stb + OFF_AL + off);
            }
#pragma unroll
            for (int ntp = 0; ntp < 4; ++ntp) {
                uint32_t off = (uint32_t)((rB + ntp*16) * MAT_STRIDE + koffB + ks*16) * 2;
                ldm_x4(bh[ntp], stb + OFF_BH + off);
                ldm_x4(bl[ntp], stb + OFF_BL + off);
            }
#pragma unroll
            for (int mt = 0; mt < 2; ++mt)
#pragma unroll
                for (int ntp = 0; ntp < 4; ++ntp) {
                    mma_bf16(acc[mt][2*ntp],   ah[mt], &bh[ntp][0]);
                    mma_bf16(acc[mt][2*ntp+1], ah[mt], &bh[ntp][2]);
                    mma_bf16(acc[mt][2*ntp],   ah[mt], &bl[ntp][0]);
                    mma_bf16(acc[mt][2*ntp+1], ah[mt], &bl[ntp][2]);
                    mma_bf16(acc[mt][2*ntp],   al[mt], &bh[ntp][0]);
                    mma_bf16(acc[mt][2*ntp+1], al[mt], &bh[ntp][2]);
                }
        }
        __syncthreads();
    }
#undef LOAD_STAGE

    // Epilogue: fragment layout -> rows r0=base+lane/4, r1=r0+8;
    // cols c..c+1 = 2*(lane&3) within each n8 tile.
#pragma unroll
    for (int mt = 0; mt < 2; ++mt) {
        int r0 = m0 + wm * 32 + mt * 16 + (lane >> 2);
#pragma unroll
        for (int nt = 0; nt < 8; ++nt) {
            int cc = n0 + wn * 64 + nt * 8 + 2 * (lane & 3);
            float b0 = bias[cc], b1 = bias[cc + 1];
            float v00 = acc[mt][nt][0] + b0, v01 = acc[mt][nt][1] + b1;
            float v10 = acc[mt][nt][2] + b0, v11 = acc[mt][nt][3] + b1;
            if (MODE == 1) {
                float2 p0; p0.x = v00; p0.y = v01;
                float2 p1; p1.x = v10; p1.y = v11;
                *(float2*)&Cout[(size_t)r0 * PD + cc]       = p0;
                *(float2*)&Cout[(size_t)(r0 + 8) * PD + cc] = p1;
            } else {
                int which = cc / PD;
                int rem = cc - which * PD;
                int h = rem >> 6, dk = rem & 63;
                int b = r0 >> 11;
                int l = r0 & 2047;     // rows r0 and r0+8 share b (tiles are 128-aligned)
                if (which == 2) {
                    float2 p0; p0.x = v00; p0.y = v01;
                    float2 p1; p1.x = v10; p1.y = v11;
                    size_t base = ((size_t)(b * PH + h) * PL) * PDK;
                    *(float2*)&g_V[base + (size_t)l * PDK + dk]       = p0;
                    *(float2*)&g_V[base + (size_t)(l + 8) * PDK + dk] = p1;
                } else {
                    float* dst = (which == 0) ? g_Q : g_K;
                    size_t base = ((size_t)(b * PH + h) * PDK + dk) * PL + l;
                    dst[base]          = v00;
                    dst[base + PL]     = v01;
                    dst[base + 8]      = v10;
                    dst[base + PL + 8] = v11;
                }
            }
        }
    }
}

// ---------------------------------------------------------------------------
// Flash attention (causal), fp32 (unchanged — passing at rel_err 1e-6)
// ---------------------------------------------------------------------------
__global__ __launch_bounds__(128, 4)
void attn_kernel()
{
    __shared__ float Qt[64][64];   // [d][q]
    __shared__ float KT[64][64];   // [d][k], reused as P[q][k]
    __shared__ float Vs[64][64];   // [k][d]

    int tid = threadIdx.x;
    int ty = tid >> 4;
    int tx = tid & 15;
    int qt = blockIdx.x;
    int bh = blockIdx.y;

    const float* Qg = g_Q + (size_t)bh * PDK * PL;
    const float* Kg = g_K + (size_t)bh * PDK * PL;
    const float* Vg = g_V + (size_t)bh * PL * PDK;

#pragma unroll
    for (int jj = 0; jj < 8; jj++) {
        int i = tid + 128 * jj;
        int d = i >> 4;
        int c4 = i & 15;
        *(float4*)(&Qt[d][4*c4]) = *(const float4*)(Qg + (size_t)d * PL + qt * 64 + 4 * c4);
    }

    float mrow[8], lrow[8], o[8][4];
#pragma unroll
    for (int i = 0; i < 8; i++) {
        mrow[i] = -INFINITY;
        lrow[i] = 0.f;
#pragma unroll
        for (int j = 0; j < 4; j++) o[i][j] = 0.f;
    }

    const int nkt = qt + 1;
    for (int kt = 0; kt < nkt; kt++) {
        __syncthreads();
#pragma unroll
        for (int jj = 0; jj < 8; jj++) {
            int i = tid + 128 * jj;
            int d = i >> 4;
            int c4 = i & 15;
            *(float4*)(&KT[d][4*c4]) =
                *(const float4*)(Kg + (size_t)d * PL + kt * 64 + 4 * c4);
            *(float4*)(&Vs[d][4*c4]) =
                *(const float4*)(Vg + (size_t)(kt * 64 + d) * PDK + 4 * c4);
        }
        __syncthreads();

        float s[8][4];
#pragma unroll
        for (int i = 0; i < 8; i++)
#pragma unroll
            for (int j = 0; j < 4; j++) s[i][j] = 0.f;

#pragma unroll
        for (int d0 = 0; d0 < 64; d0 += 2) {
            float bf[2][4], af[2][8];
#pragma unroll
            for (int c = 0; c < 2; c++) {
                *(float4*)(bf[c]) = *(const float4*)(&KT[d0+c][4*tx]);
                *(float4*)(af[c])     = *(const float4*)(&Qt[d0+c][8*ty]);
                *(float4*)(af[c] + 4) = *(const float4*)(&Qt[d0+c][8*ty + 4]);
            }
#pragma unroll
            for (int c = 0; c < 2; c++)
#pragma unroll
                for (int i = 0; i < 8; i++)
#pragma unroll
                    for (int j = 0; j < 4; j++)
                        s[i][j] += af[c][i] * bf[c][j];
        }

        const bool diag = (kt == qt);
#pragma unroll
        for (int i = 0; i < 8; i++)
#pragma unroll
            for (int j = 0; j < 4; j++) {
                float v = s[i][j] * 0.125f;
                if (diag && (4*tx + j) > (8*ty + i)) v = -1e30f;
                s[i][j] = v;
            }

#pragma unroll
        for (int i = 0; i < 8; i++) {
            float rm = fmaxf(fmaxf(s[i][0], s[i][1]), fmaxf(s[i][2], s[i][3]));
#pragma unroll
            for (int off = 8; off > 0; off >>= 1)
                rm = fmaxf(rm, __shfl_xor_sync(0xffffffffu, rm, off));
            float mn = fmaxf(mrow[i], rm);
            float alpha = __expf(mrow[i] - mn);
            mrow[i] = mn;
            float rs = 0.f;
#pragma unroll
            for (int j = 0; j < 4; j++) {
                s[i][j] = __expf(s[i][j] - mn);
                rs += s[i][j];
            }
#pragma unroll
            for (int off = 8; off > 0; off >>= 1)
                rs += __shfl_xor_sync(0xffffffffu, rs, off);
            lrow[i] = lrow[i] * alpha + rs;
#pragma unroll
            for (int j = 0; j < 4; j++) o[i][j] *= alpha;
        }

        __syncthreads();
#pragma unroll
        for (int i = 0; i < 8; i++) {
            float4 pv;
            pv.x = s[i][0]; pv.y = s[i][1]; pv.z = s[i][2]; pv.w = s[i][3];
            *(float4*)(&KT[8*ty + i][4*tx]) = pv;
        }
        __syncthreads();

#pragma unroll
        for (int kc = 0; kc < 16; kc++) {
            float pf[8][4], vf[4][4];
#pragma unroll
            for (int i = 0; i < 8; i++)
                *(float4*)(pf[i]) = *(const float4*)(&KT[8*ty + i][4*kc]);
#pragma unroll
            for (int c = 0; c < 4; c++)
                *(float4*)(vf[c]) = *(const float4*)(&Vs[4*kc + c][4*tx]);
#pragma unroll
            for (int c = 0; c < 4; c++)
#pragma unroll
                for (int i = 0; i < 8; i++)
#pragma unroll
                    for (int j = 0; j < 4; j++)
                        o[i][j] += pf[i][c] * vf[c][j];
        }
    }

    int b = bh / PH;
    int h = bh - b * PH;
#pragma unroll
    for (int i = 0; i < 8; i++) {
        float inv = 1.f / lrow[i];
        int q = qt * 64 + 8 * ty + i;
        float4 ov;
        ov.x = o[i][0] * inv;
        ov.y = o[i][1] * inv;
        ov.z = o[i][2] * inv;
        ov.w = o[i][3] * inv;
        *(float4*)(g_A + ((size_t)b * PL + q) * PD + h * PDK + 4 * tx) = ov;
    }
}

// ---------------------------------------------------------------------------
extern "C" void kernel_launch(void* const* d_in, const int* in_sizes, int n_in,
                              void* d_out, int out_size)
{
    const float* x    = (const float*)d_in[0];
    // d_in[1] = additive causal mask — implemented analytically, unused
    const float* Wqkv = (const float*)d_in[2];
    const float* bqkv = (const float*)d_in[3];
    const float* Wo   = (const float*)d_in[4];
    const float* bo   = (const float*)d_in[5];
    float* out = (float*)d_out;

    cudaFuncSetAttribute(tc_gemm<0>, cudaFuncAttributeMaxDynamicSharedMemorySize, TGSMEM);
    cudaFuncSetAttribute(tc_gemm<1>, cudaFuncAttributeMaxDynamicSharedMemorySize, TGSMEM);

    // Prep: splits (+ weight transposes)
    split_pair<false><<<M1*PD/512, 256>>>(x, g_xh, g_xl, M1*PD/2);
    transpose_split<<<dim3(NQKV/32, PD/32), dim3(32, 8)>>>(Wqkv, g_Wqh, g_Wql, PD, NQKV);
    transpose_split<<<dim3(PD/32, PD/32), dim3(32, 8)>>>(Wo, g_Woh, g_Wol, PD, PD);

    // 1) QKV projection (HMMA bf16-split)
    tc_gemm<0><<<dim3(NQKV/128, M1/128), 256, TGSMEM>>>(g_xh, g_xl, g_Wqh, g_Wql, bqkv, nullptr);

    // 2) Causal flash attention
    attn_kernel<<<dim3(PL/64, PB*PH), 128>>>();

    // 3) Split attention output, then output projection
    split_pair<true><<<M1*PD/512, 256>>>(nullptr, g_Ah, g_Al, M1*PD/2);
    tc_gemm<1><<<dim3(PD/128, M1/128), 256, TGSMEM>>>(g_Ah, g_Al, g_Woh, g_Wol, bo, out);
}

// round 6
// speedup vs baseline: 3.7963x; 3.7963x over previous
#include <cuda_runtime.h>
#include <math.h>
#include <stdint.h>

// Problem constants
#define PB 2
#define PL 2048
#define PD 768
#define PH 12
#define PDK 64
#define M1 (PB*PL)        // 4096
#define N1 (3*PD)         // 2304
#define K1 PD             // 768

// Scratch (allocation-free rule: __device__ globals)
// Q, K stored TRANSPOSED per head: [b][h][dk][l]; V natural: [b][h][l][dk]
__device__ float g_Q[PB*PH*PDK*PL];
__device__ float g_K[PB*PH*PDK*PL];
__device__ float g_V[PB*PH*PL*PDK];
__device__ float g_A[PB*PL*PD];       // attention output, [b][l][h*dk]

typedef unsigned long long u64;

// ---------------------------------------------------------------------------
// f32x2 packed-math helpers (Blackwell FFMA2 path)
// ---------------------------------------------------------------------------
__device__ __forceinline__ void fma2(u64& d, u64 a, u64 b) {
    asm("fma.rn.f32x2 %0, %1, %2, %0;" : "+l"(d) : "l"(a), "l"(b));
}
__device__ __forceinline__ void mul2(u64& d, u64 a) {
    asm("mul.rn.f32x2 %0, %0, %1;" : "+l"(d) : "l"(a));
}
__device__ __forceinline__ u64 pack2(float x, float y) {
    u64 r;
    asm("mov.b64 %0, {%1, %2};" : "=l"(r) : "f"(x), "f"(y));
    return r;
}
__device__ __forceinline__ void unpack2(u64 v, float& x, float& y) {
    asm("mov.b64 {%0, %1}, %2;" : "=f"(x), "=f"(y) : "l"(v));
}

__device__ __forceinline__ void cp_async16(void* smem_dst, const void* gmem_src) {
    unsigned sm = (unsigned)__cvta_generic_to_shared(smem_dst);
    asm volatile("cp.async.cg.shared.global [%0], [%1], 16;\n" :: "r"(sm), "l"(gmem_src));
}
__device__ __forceinline__ void cp_async_commit() {
    asm volatile("cp.async.commit_group;\n" ::: "memory");
}

// ---------------------------------------------------------------------------
// Tiled SGEMM (f32x2): C[M,N] = A[M,K] @ B[K,N] + bias
// BM=BN=128, BK=16, 256 threads, 8x8 per thread, double-buffered.
// Accumulators are f32x2 pairs along N: acc2[i][j2] = cols (2*j2, 2*j2+1).
// MODE 0: A = x, epilogue scatters into g_Q/g_K (transposed) / g_V
// MODE 1: A = g_A, epilogue writes C (final output) with bias
// ---------------------------------------------------------------------------
template<int MODE>
__global__ __launch_bounds__(256, 2)
void sgemm_kernel(const float* __restrict__ Ain, const float* __restrict__ Bm,
                  const float* __restrict__ bias, float* __restrict__ C,
                  int M, int N, int K)
{
    __shared__ float As[2][16][132];   // transposed A tile, padded (132*4 % 16 == 0)
    __shared__ float Bs[2][16][128];

    const float* A = (MODE == 1) ? (const float*)g_A : Ain;

    int tid = threadIdx.x;
    int tm = tid >> 4;          // 0..15
    int tn = tid & 15;          // 0..15
    int m0 = blockIdx.y * 128;
    int n0 = blockIdx.x * 128;

    u64 acc2[8][4];
#pragma unroll
    for (int i = 0; i < 8; i++)
#pragma unroll
        for (int j = 0; j < 4; j++) acc2[i][j] = 0ull;

    float4 a_st[2];

    // ---- prologue: stage tile 0 ----
#pragma unroll
    for (int jj = 0; jj < 2; jj++) {
        int i = tid + 256 * jj;
        int row = i >> 2, c4 = i & 3;
        a_st[jj] = *(const float4*)(A + (size_t)(m0 + row) * K + 4 * c4);
    }
#pragma unroll
    for (int jj = 0; jj < 2; jj++) {
        int i = tid + 256 * jj;
        int kr = i >> 5, c4 = i & 31;
        cp_async16(&Bs[0][kr][4 * c4], Bm + (size_t)kr * N + n0 + 4 * c4);
    }
#pragma unroll
    for (int jj = 0; jj < 2; jj++) {
        int i = tid + 256 * jj;
        int row = i >> 2, c4 = i & 3;
        As[0][4*c4+0][row] = a_st[jj].x;
        As[0][4*c4+1][row] = a_st[jj].y;
        As[0][4*c4+2][row] = a_st[jj].z;
        As[0][4*c4+3][row] = a_st[jj].w;
    }
    cp_async_commit();
    asm volatile("cp.async.wait_group 0;\n" ::: "memory");
    __syncthreads();

    const int NIT = K / 16;
    for (int it = 0; it < NIT; it++) {
        int cur = it & 1, nxt = cur ^ 1;
        int k0n = (it + 1) * 16;
        bool has_next = (it + 1) < NIT;

        if (has_next) {
#pragma unroll
            for (int jj = 0; jj < 2; jj++) {
                int i = tid + 256 * jj;
                int row = i >> 2, c4 = i & 3;
                a_st[jj] = *(const float4*)(A + (size_t)(m0 + row) * K + k0n + 4 * c4);
            }
#pragma unroll
            for (int jj = 0; jj < 2; jj++) {
                int i = tid + 256 * jj;
                int kr = i >> 5, c4 = i & 31;
                cp_async16(&Bs[nxt][kr][4 * c4], Bm + (size_t)(k0n + kr) * N + n0 + 4 * c4);
            }
            cp_async_commit();
        }

#pragma unroll
        for (int kk = 0; kk < 16; kk++) {
            float af[8];
            *(float4*)(af)     = *(const float4*)(&As[cur][kk][tm*8]);
            *(float4*)(af + 4) = *(const float4*)(&As[cur][kk][tm*8 + 4]);
            ulonglong2 b01 = *(const ulonglong2*)(&Bs[cur][kk][tn*8]);
            ulonglong2 b23 = *(const ulonglong2*)(&Bs[cur][kk][tn*8 + 4]);
            u64 bp[4] = {b01.x, b01.y, b23.x, b23.y};
#pragma unroll
            for (int i = 0; i < 8; i++) {
                u64 ar = pack2(af[i], af[i]);
#pragma unroll
                for (int j = 0; j < 4; j++)
                    fma2(acc2[i][j], ar, bp[j]);
            }
        }

        if (has_next) {
#pragma unroll
            for (int jj = 0; jj < 2; jj++) {
                int i = tid + 256 * jj;
                int row = i >> 2, c4 = i & 3;
                As[nxt][4*c4+0][row] = a_st[jj].x;
                As[nxt][4*c4+1][row] = a_st[jj].y;
                As[nxt][4*c4+2][row] = a_st[jj].z;
                As[nxt][4*c4+3][row] = a_st[jj].w;
            }
            asm volatile("cp.async.wait_group 0;\n" ::: "memory");
        }
        __syncthreads();
    }

    // Unpack accumulators
    float acc[8][8];
#pragma unroll
    for (int i = 0; i < 8; i++)
#pragma unroll
        for (int j = 0; j < 4; j++)
            unpack2(acc2[i][j], acc[i][2*j], acc[i][2*j+1]);

    if (MODE == 0) {
#pragma unroll
        for (int j = 0; j < 8; j++) {
            int c = n0 + tn * 8 + j;
            float bv = bias[c];
            int which = c / PD;
            int rem = c - which * PD;
            int h = rem >> 6;
            int dk = rem & 63;
            int r0 = m0 + tm * 8;
            int b = r0 >> 11;
            int l0 = r0 & 2047;
            if (which == 2) {
#pragma unroll
                for (int i = 0; i < 8; i++)
                    g_V[(((size_t)(b * PH + h)) * PL + l0 + i) * PDK + dk] = acc[i][j] + bv;
            } else {
                float* dst = (which == 0) ? g_Q : g_K;
                float* base = dst + (((size_t)(b * PH + h)) * PDK + dk) * PL + l0;
                float4 c0, c1;
                c0.x = acc[0][j] + bv; c0.y = acc[1][j] + bv;
                c0.z = acc[2][j] + bv; c0.w = acc[3][j] + bv;
                c1.x = acc[4][j] + bv; c1.y = acc[5][j] + bv;
                c1.z = acc[6][j] + bv; c1.w = acc[7][j] + bv;
                *(float4*)(base)     = c0;
                *(float4*)(base + 4) = c1;
            }
        }
    } else {
        float4 bv0 = *(const float4*)(bias + n0 + tn * 8);
        float4 bv1 = *(const float4*)(bias + n0 + tn * 8 + 4);
#pragma unroll
        for (int i = 0; i < 8; i++) {
            int r = m0 + tm * 8 + i;
            float4 c0, c1;
            c0.x = acc[i][0] + bv0.x; c0.y = acc[i][1] + bv0.y;
            c0.z = acc[i][2] + bv0.z; c0.w = acc[i][3] + bv0.w;
            c1.x = acc[i][4] + bv1.x; c1.y = acc[i][5] + bv1.y;
            c1.z = acc[i][6] + bv1.z; c1.w = acc[i][7] + bv1.w;
            *(float4*)(C + (size_t)r * N + n0 + tn * 8)     = c0;
            *(float4*)(C + (size_t)r * N + n0 + tn * 8 + 4) = c1;
        }
    }
}

// ---------------------------------------------------------------------------
// Flash attention (causal), fp32 with f32x2 inner products.
// Grid: (L/64, B*H). Block: 128 threads (8x16), 8x4 fragment per thread.
// QK: pairs along queries (Q rows adjacent in Qt[d][q]).
// PV: pairs along head-dim (V cols adjacent in Vs[k][d]).
// ---------------------------------------------------------------------------
__global__ __launch_bounds__(128, 4)
void attn_kernel()
{
    __shared__ float Qt[64][64];   // [d][q]
    __shared__ float KT[64][64];   // [d][k], reused as P[q][k]
    __shared__ float Vs[64][64];   // [k][d]

    int tid = threadIdx.x;
    int ty = tid >> 4;      // 0..7  -> query rows 8*ty..
    int tx = tid & 15;      // 0..15 -> key/dim cols 4*tx..
    int qt = blockIdx.x;
    int bh = blockIdx.y;

    const float* Qg = g_Q + (size_t)bh * PDK * PL;  // [d][l]
    const float* Kg = g_K + (size_t)bh * PDK * PL;
    const float* Vg = g_V + (size_t)bh * PL * PDK;  // [l][d]

#pragma unroll
    for (int jj = 0; jj < 8; jj++) {
        int i = tid + 128 * jj;
        int d = i >> 4;
        int c4 = i & 15;
        *(float4*)(&Qt[d][4*c4]) = *(const float4*)(Qg + (size_t)d * PL + qt * 64 + 4 * c4);
    }

    float mrow[8], lrow[8];
    u64 o2[8][2];               // o2[i][j2] = cols (2*j2, 2*j2+1) pair
#pragma unroll
    for (int i = 0; i < 8; i++) {
        mrow[i] = -INFINITY;
        lrow[i] = 0.f;
        o2[i][0] = 0ull;
        o2[i][1] = 0ull;
    }

    const int nkt = qt + 1;
    for (int kt = 0; kt < nkt; kt++) {
        __syncthreads();
#pragma unroll
        for (int jj = 0; jj < 8; jj++) {
            int i = tid + 128 * jj;
            int d = i >> 4;
            int c4 = i & 15;
            *(float4*)(&KT[d][4*c4]) =
                *(const float4*)(Kg + (size_t)d * PL + kt * 64 + 4 * c4);
            *(float4*)(&Vs[d][4*c4]) =
                *(const float4*)(Vg + (size_t)(kt * 64 + d) * PDK + 4 * c4);
        }
        __syncthreads();

        // S = Q^T' @ K : pairs along i.  s2[ip][j] = rows (2ip, 2ip+1), col j
        u64 s2[4][4];
#pragma unroll
        for (int ip = 0; ip < 4; ip++)
#pragma unroll
            for (int j = 0; j < 4; j++) s2[ip][j] = 0ull;

#pragma unroll
        for (int d = 0; d < 64; d++) {
            ulonglong2 a01 = *(const ulonglong2*)(&Qt[d][8*ty]);
            ulonglong2 a23 = *(const ulonglong2*)(&Qt[d][8*ty + 4]);
            u64 ap[4] = {a01.x, a01.y, a23.x, a23.y};
            float4 bf = *(const float4*)(&KT[d][4*tx]);
            u64 bp[4] = {pack2(bf.x, bf.x), pack2(bf.y, bf.y),
                         pack2(bf.z, bf.z), pack2(bf.w, bf.w)};
#pragma unroll
            for (int ip = 0; ip < 4; ip++)
#pragma unroll
                for (int j = 0; j < 4; j++)
                    fma2(s2[ip][j], ap[ip], bp[j]);
        }

        // Unpack to s[8][4]
        float s[8][4];
#pragma unroll
        for (int ip = 0; ip < 4; ip++)
#pragma unroll
            for (int j = 0; j < 4; j++)
                unpack2(s2[ip][j], s[2*ip][j], s[2*ip+1][j]);

        const bool diag = (kt == qt);
#pragma unroll
        for (int i = 0; i < 8; i++)
#pragma unroll
            for (int j = 0; j < 4; j++) {
                float v = s[i][j] * 0.125f;
                if (diag && (4*tx + j) > (8*ty + i)) v = -1e30f;
                s[i][j] = v;
            }

        // Online softmax; row shared by the 16 tx-lanes (half-warp)
#pragma unroll
        for (int i = 0; i < 8; i++) {
            float rm = fmaxf(fmaxf(s[i][0], s[i][1]), fmaxf(s[i][2], s[i][3]));
#pragma unroll
            for (int off = 8; off > 0; off >>= 1)
                rm = fmaxf(rm, __shfl_xor_sync(0xffffffffu, rm, off));
            float mn = fmaxf(mrow[i], rm);
            float alpha = __expf(mrow[i] - mn);
            mrow[i] = mn;
            float rs = 0.f;
#pragma unroll
            for (int j = 0; j < 4; j++) {
                s[i][j] = __expf(s[i][j] - mn);
                rs += s[i][j];
            }
#pragma unroll
            for (int off = 8; off > 0; off >>= 1)
                rs += __shfl_xor_sync(0xffffffffu, rs, off);
            lrow[i] = lrow[i] * alpha + rs;
            u64 al2 = pack2(alpha, alpha);
            mul2(o2[i][0], al2);
            mul2(o2[i][1], al2);
        }

        __syncthreads();   // all threads done reading KT as K^T
        // Store P natural [q][k]
#pragma unroll
        for (int i = 0; i < 8; i++) {
            float4 pv;
            pv.x = s[i][0]; pv.y = s[i][1]; pv.z = s[i][2]; pv.w = s[i][3];
            *(float4*)(&KT[8*ty + i][4*tx]) = pv;
        }
        __syncthreads();

        // O += P @ V : pairs along head-dim j
#pragma unroll
        for (int kc = 0; kc < 16; kc++) {
            u64 vp[4][2];
#pragma unroll
            for (int c = 0; c < 4; c++) {
                ulonglong2 v2 = *(const ulonglong2*)(&Vs[4*kc + c][4*tx]);
                vp[c][0] = v2.x;
                vp[c][1] = v2.y;
            }
#pragma unroll
            for (int i = 0; i < 8; i++) {
                float4 pf = *(const float4*)(&KT[8*ty + i][4*kc]);
                float pfa[4] = {pf.x, pf.y, pf.z, pf.w};
#pragma unroll
                for (int c = 0; c < 4; c++) {
                    u64 pr = pack2(pfa[c], pfa[c]);
                    fma2(o2[i][0], pr, vp[c][0]);
                    fma2(o2[i][1], pr, vp[c][1]);
                }
            }
        }
    }

    // Normalize and write to g_A: [b][l][h*64 + d]
    int b = bh / PH;
    int h = bh - b * PH;
#pragma unroll
    for (int i = 0; i < 8; i++) {
        float inv = 1.f / lrow[i];
        int q = qt * 64 + 8 * ty + i;
        float o0, o1, o2f, o3;
        unpack2(o2[i][0], o0, o1);
        unpack2(o2[i][1], o2f, o3);
        float4 ov;
        ov.x = o0 * inv;
        ov.y = o1 * inv;
        ov.z = o2f * inv;
        ov.w = o3 * inv;
        *(float4*)(g_A + ((size_t)b * PL + q) * PD + h * PDK + 4 * tx) = ov;
    }
}

// ---------------------------------------------------------------------------
extern "C" void kernel_launch(void* const* d_in, const int* in_sizes, int n_in,
                              void* d_out, int out_size)
{
    const float* x    = (const float*)d_in[0];
    // d_in[1] = additive causal mask — logic implemented directly, unused
    const float* Wqkv = (const float*)d_in[2];
    const float* bqkv = (const float*)d_in[3];
    const float* Wo   = (const float*)d_in[4];
    const float* bo   = (const float*)d_in[5];
    float* out = (float*)d_out;

    // 1) QKV projection: [4096,768] @ [768,2304] -> Q^T/K^T/V scratch
    dim3 g1(N1 / 128, M1 / 128);   // (18, 32)
    sgemm_kernel<0><<<g1, 256>>>(x, Wqkv, bqkv, nullptr, M1, N1, K1);

    // 2) Causal flash attention per (b,h), 64-query tiles
    dim3 g2(PL / 64, PB * PH);     // (32, 24)
    attn_kernel<<<g2, 128>>>();

    // 3) Output projection: [4096,768] @ [768,768] + bo -> out
    dim3 g3(PD / 128, M1 / 128);   // (6, 32)
    sgemm_kernel<1><<<g3, 256>>>(nullptr, Wo, bo, out, M1, PD, K1);
}

// round 9
// speedup vs baseline: 4.9398x; 1.3012x over previous
#include <cuda_runtime.h>
#include <math.h>
#include <stdint.h>

// Problem constants
#define PB 2
#define PL 2048
#define PD 768
#define PH 12
#define PDK 64
#define M1 (PB*PL)        // 4096
#define N1 (3*PD)         // 2304
#define K1 PD             // 768

// Scratch (allocation-free rule: __device__ globals)
// Q, K stored TRANSPOSED per head: [b][h][dk][l]; V natural: [b][h][l][dk]
__device__ float g_Q[PB*PH*PDK*PL];
__device__ float g_K[PB*PH*PDK*PL];
__device__ float g_V[PB*PH*PL*PDK];
__device__ float g_A[PB*PL*PD];       // attention output, [b][l][h*dk]

__device__ __forceinline__ void cp_async16(void* smem_dst, const void* gmem_src) {
    unsigned sm = (unsigned)__cvta_generic_to_shared(smem_dst);
    asm volatile("cp.async.cg.shared.global [%0], [%1], 16;\n" :: "r"(sm), "l"(gmem_src));
}
__device__ __forceinline__ void cp_async_commit() {
    asm volatile("cp.async.commit_group;\n" ::: "memory");
}
__device__ __forceinline__ void cp_async_wait_all() {
    asm volatile("cp.async.wait_group 0;\n" ::: "memory");
}

// ---------------------------------------------------------------------------
// Tiled SGEMM: C[M,N] = A[M,K] @ B[K,N] + bias  (identical to R3 — 44 TF/s)
// ---------------------------------------------------------------------------
template<int MODE>
__global__ __launch_bounds__(256, 2)
void sgemm_kernel(const float* __restrict__ Ain, const float* __restrict__ Bm,
                  const float* __restrict__ bias, float* __restrict__ C,
                  int M, int N, int K)
{
    __shared__ float As[2][16][132];
    __shared__ float Bs[2][16][128];

    const float* A = (MODE == 1) ? (const float*)g_A : Ain;

    int tid = threadIdx.x;
    int tm = tid >> 4;
    int tn = tid & 15;
    int m0 = blockIdx.y * 128;
    int n0 = blockIdx.x * 128;

    float acc[8][8];
#pragma unroll
    for (int i = 0; i < 8; i++)
#pragma unroll
        for (int j = 0; j < 8; j++) acc[i][j] = 0.f;

    float4 a_st[2];

#pragma unroll
    for (int jj = 0; jj < 2; jj++) {
        int i = tid + 256 * jj;
        int row = i >> 2, c4 = i & 3;
        a_st[jj] = *(const float4*)(A + (size_t)(m0 + row) * K + 4 * c4);
    }
#pragma unroll
    for (int jj = 0; jj < 2; jj++) {
        int i = tid + 256 * jj;
        int kr = i >> 5, c4 = i & 31;
        cp_async16(&Bs[0][kr][4 * c4], Bm + (size_t)kr * N + n0 + 4 * c4);
    }
#pragma unroll
    for (int jj = 0; jj < 2; jj++) {
        int i = tid + 256 * jj;
        int row = i >> 2, c4 = i & 3;
        As[0][4*c4+0][row] = a_st[jj].x;
        As[0][4*c4+1][row] = a_st[jj].y;
        As[0][4*c4+2][row] = a_st[jj].z;
        As[0][4*c4+3][row] = a_st[jj].w;
    }
    cp_async_commit();
    cp_async_wait_all();
    __syncthreads();

    const int NIT = K / 16;
    for (int it = 0; it < NIT; it++) {
        int cur = it & 1, nxt = cur ^ 1;
        int k0n = (it + 1) * 16;
        bool has_next = (it + 1) < NIT;

        if (has_next) {
#pragma unroll
            for (int jj = 0; jj < 2; jj++) {
                int i = tid + 256 * jj;
                int row = i >> 2, c4 = i & 3;
                a_st[jj] = *(const float4*)(A + (size_t)(m0 + row) * K + k0n + 4 * c4);
            }
#pragma unroll
            for (int jj = 0; jj < 2; jj++) {
                int i = tid + 256 * jj;
                int kr = i >> 5, c4 = i & 31;
                cp_async16(&Bs[nxt][kr][4 * c4], Bm + (size_t)(k0n + kr) * N + n0 + 4 * c4);
            }
            cp_async_commit();
        }

#pragma unroll
        for (int kk = 0; kk < 16; kk++) {
            float af[8], bf[8];
            *(float4*)(af)     = *(const float4*)(&As[cur][kk][tm*8]);
            *(float4*)(af + 4) = *(const float4*)(&As[cur][kk][tm*8 + 4]);
            *(float4*)(bf)     = *(const float4*)(&Bs[cur][kk][tn*8]);
            *(float4*)(bf + 4) = *(const float4*)(&Bs[cur][kk][tn*8 + 4]);
#pragma unroll
            for (int i = 0; i < 8; i++)
#pragma unroll
                for (int j = 0; j < 8; j++)
                    acc[i][j] += af[i] * bf[j];
        }

        if (has_next) {
#pragma unroll
            for (int jj = 0; jj < 2; jj++) {
                int i = tid + 256 * jj;
                int row = i >> 2, c4 = i & 3;
                As[nxt][4*c4+0][row] = a_st[jj].x;
                As[nxt][4*c4+1][row] = a_st[jj].y;
                As[nxt][4*c4+2][row] = a_st[jj].z;
                As[nxt][4*c4+3][row] = a_st[jj].w;
            }
            cp_async_wait_all();
        }
        __syncthreads();
    }

    if (MODE == 0) {
#pragma unroll
        for (int j = 0; j < 8; j++) {
            int c = n0 + tn * 8 + j;
            float bv = bias[c];
            int which = c / PD;
            int rem = c - which * PD;
            int h = rem >> 6;
            int dk = rem & 63;
            int r0 = m0 + tm * 8;
            int b = r0 >> 11;
            int l0 = r0 & 2047;
            if (which == 2) {
#pragma unroll
                for (int i = 0; i < 8; i++)
                    g_V[(((size_t)(b * PH + h)) * PL + l0 + i) * PDK + dk] = acc[i][j] + bv;
            } else {
                float* dst = (which == 0) ? g_Q : g_K;
                float* base = dst + (((size_t)(b * PH + h)) * PDK + dk) * PL + l0;
                float4 c0, c1;
                c0.x = acc[0][j] + bv; c0.y = acc[1][j] + bv;
                c0.z = acc[2][j] + bv; c0.w = acc[3][j] + bv;
                c1.x = acc[4][j] + bv; c1.y = acc[5][j] + bv;
                c1.z = acc[6][j] + bv; c1.w = acc[7][j] + bv;
                *(float4*)(base)     = c0;
                *(float4*)(base + 4) = c1;
            }
        }
    } else {
        float4 bv0 = *(const float4*)(bias + n0 + tn * 8);
        float4 bv1 = *(const float4*)(bias + n0 + tn * 8 + 4);
#pragma unroll
        for (int i = 0; i < 8; i++) {
            int r = m0 + tm * 8 + i;
            float4 c0, c1;
            c0.x = acc[i][0] + bv0.x; c0.y = acc[i][1] + bv0.y;
            c0.z = acc[i][2] + bv0.z; c0.w = acc[i][3] + bv0.w;
            c1.x = acc[i][4] + bv1.x; c1.y = acc[i][5] + bv1.y;
            c1.z = acc[i][6] + bv1.z; c1.w = acc[i][7] + bv1.w;
            *(float4*)(C + (size_t)r * N + n0 + tn * 8)     = c0;
            *(float4*)(C + (size_t)r * N + n0 + tn * 8 + 4) = c1;
        }
    }
}

// ---------------------------------------------------------------------------
// Flash attention (causal), fp32, v3: balanced pairing + separate P buffer.
// Grid: (16, B*H). CTA i processes query tiles i and 31-i (33 key tiles each).
// Block: 128 threads (8x16), 8x4 fragment per thread.
// Smem (dynamic, 64KB): Qt[d][q], KT[d][k], Vs[k][d], Ps[q][k].
// Scale 1/8 folded into Q load. 3 syncs per key tile.
// ---------------------------------------------------------------------------
#define ATT_QT   0
#define ATT_KT   16384
#define ATT_VS   32768
#define ATT_PS   49152
#define ATT_SMEM 65536

__device__ __forceinline__ void attn_process_tile(
    float* sm, int qt, int bh, int ty, int tx, int tid)
{
    float (*Qt)[64] = (float(*)[64])(sm + ATT_QT/4);
    float (*KT)[64] = (float(*)[64])(sm + ATT_KT/4);
    float (*Vs)[64] = (float(*)[64])(sm + ATT_VS/4);
    float (*Ps)[64] = (float(*)[64])(sm + ATT_PS/4);

    const float* Qg = g_Q + (size_t)bh * PDK * PL;  // [d][l]
    const float* Kg = g_K + (size_t)bh * PDK * PL;
    const float* Vg = g_V + (size_t)bh * PL * PDK;  // [l][d]

    // Load Q^T tile scaled by 1/8: Qt[d][q]
#pragma unroll
    for (int jj = 0; jj < 8; jj++) {
        int i = tid + 128 * jj;
        int d = i >> 4;
        int c4 = i & 15;
        float4 qv = *(const float4*)(Qg + (size_t)d * PL + qt * 64 + 4 * c4);
        qv.x *= 0.125f; qv.y *= 0.125f; qv.z *= 0.125f; qv.w *= 0.125f;
        *(float4*)(&Qt[d][4*c4]) = qv;
    }

    float mrow[8], lrow[8], o[8][4];
#pragma unroll
    for (int i = 0; i < 8; i++) {
        mrow[i] = -INFINITY;
        lrow[i] = 0.f;
#pragma unroll
        for (int j = 0; j < 4; j++) o[i][j] = 0.f;
    }

    const int nkt = qt + 1;
    for (int kt = 0; kt < nkt; kt++) {
        __syncthreads();   // prior PV reads of Ps/Vs (and QK reads of KT) done
#pragma unroll
        for (int jj = 0; jj < 8; jj++) {
            int i = tid + 128 * jj;
            int d = i >> 4;
            int c4 = i & 15;
            *(float4*)(&KT[d][4*c4]) =
                *(const float4*)(Kg + (size_t)d * PL + kt * 64 + 4 * c4);
            *(float4*)(&Vs[d][4*c4]) =
                *(const float4*)(Vg + (size_t)(kt * 64 + d) * PDK + 4 * c4);
        }
        __syncthreads();

        // S = Q^T' @ K
        float s[8][4];
#pragma unroll
        for (int i = 0; i < 8; i++)
#pragma unroll
            for (int j = 0; j < 4; j++) s[i][j] = 0.f;

#pragma unroll
        for (int d0 = 0; d0 < 64; d0 += 2) {
            float bf[2][4], af[2][8];
#pragma unroll
            for (int c = 0; c < 2; c++) {
                *(float4*)(bf[c]) = *(const float4*)(&KT[d0+c][4*tx]);
                *(float4*)(af[c])     = *(const float4*)(&Qt[d0+c][8*ty]);
                *(float4*)(af[c] + 4) = *(const float4*)(&Qt[d0+c][8*ty + 4]);
            }
#pragma unroll
            for (int c = 0; c < 2; c++)
#pragma unroll
                for (int i = 0; i < 8; i++)
#pragma unroll
                    for (int j = 0; j < 4; j++)
                        s[i][j] += af[c][i] * bf[c][j];
        }

        // Causal mask (scale already folded into Q)
        if (kt == qt) {
#pragma unroll
            for (int i = 0; i < 8; i++)
#pragma unroll
                for (int j = 0; j < 4; j++)
                    if ((4*tx + j) > (8*ty + i)) s[i][j] = -1e30f;
        }

        // Online softmax; row shared by the 16 tx-lanes
#pragma unroll
        for (int i = 0; i < 8; i++) {
            float rm = fmaxf(fmaxf(s[i][0], s[i][1]), fmaxf(s[i][2], s[i][3]));
#pragma unroll
            for (int off = 8; off > 0; off >>= 1)
                rm = fmaxf(rm, __shfl_xor_sync(0xffffffffu, rm, off));
            float mn = fmaxf(mrow[i], rm);
            float alpha = __expf(mrow[i] - mn);
            mrow[i] = mn;
            float rs = 0.f;
#pragma unroll
            for (int j = 0; j < 4; j++) {
                s[i][j] = __expf(s[i][j] - mn);
                rs += s[i][j];
            }
#pragma unroll
            for (int off = 8; off > 0; off >>= 1)
                rs += __shfl_xor_sync(0xffffffffu, rs, off);
            lrow[i] = lrow[i] * alpha + rs;
#pragma unroll
            for (int j = 0; j < 4; j++) o[i][j] *= alpha;
        }

        // Store P into its own buffer (no race with KT)
#pragma unroll
        for (int i = 0; i < 8; i++) {
            float4 pv;
            pv.x = s[i][0]; pv.y = s[i][1]; pv.z = s[i][2]; pv.w = s[i][3];
            *(float4*)(&Ps[8*ty + i][4*tx]) = pv;
        }
        __syncthreads();

        // O += P @ V
#pragma unroll
        for (int kc = 0; kc < 16; kc++) {
            float pf[8][4], vf[4][4];
#pragma unroll
            for (int i = 0; i < 8; i++)
                *(float4*)(pf[i]) = *(const float4*)(&Ps[8*ty + i][4*kc]);
#pragma unroll
            for (int c = 0; c < 4; c++)
                *(float4*)(vf[c]) = *(const float4*)(&Vs[4*kc + c][4*tx]);
#pragma unroll
            for (int c = 0; c < 4; c++)
#pragma unroll
                for (int i = 0; i < 8; i++)
#pragma unroll
                    for (int j = 0; j < 4; j++)
                        o[i][j] += pf[i][c] * vf[c][j];
        }
    }

    int b = bh / PH;
    int h = bh - b * PH;
#pragma unroll
    for (int i = 0; i < 8; i++) {
        float inv = 1.f / lrow[i];
        int q = qt * 64 + 8 * ty + i;
        float4 ov;
        ov.x = o[i][0] * inv;
        ov.y = o[i][1] * inv;
        ov.z = o[i][2] * inv;
        ov.w = o[i][3] * inv;
        *(float4*)(g_A + ((size_t)b * PL + q) * PD + h * PDK + 4 * tx) = ov;
    }
}

__global__ __launch_bounds__(128, 3)
void attn_kernel()
{
    extern __shared__ float sm[];
    int tid = threadIdx.x;
    int ty = tid >> 4;
    int tx = tid & 15;
    int bh = blockIdx.y;
    int i  = blockIdx.x;               // 0..15

    attn_process_tile(sm, i, bh, ty, tx, tid);        // qt+1 = i+1 key tiles
    __syncthreads();                                   // Qt reuse guard
    attn_process_tile(sm, 31 - i, bh, ty, tx, tid);   // 32-i key tiles  (total 33)
}

// ---------------------------------------------------------------------------
extern "C" void kernel_launch(void* const* d_in, const int* in_sizes, int n_in,
                              void* d_out, int out_size)
{
    const float* x    = (const float*)d_in[0];
    // d_in[1] = additive causal mask — logic implemented directly, unused
    const float* Wqkv = (const float*)d_in[2];
    const float* bqkv = (const float*)d_in[3];
    const float* Wo   = (const float*)d_in[4];
    const float* bo   = (const float*)d_in[5];
    float* out = (float*)d_out;

    cudaFuncSetAttribute(attn_kernel, cudaFuncAttributeMaxDynamicSharedMemorySize, ATT_SMEM);

    // 1) QKV projection
    dim3 g1(N1 / 128, M1 / 128);   // (18, 32)
    sgemm_kernel<0><<<g1, 256>>>(x, Wqkv, bqkv, nullptr, M1, N1, K1);

    // 2) Causal flash attention, balanced pairing: CTA i -> qts {i, 31-i}
    dim3 g2(16, PB * PH);          // (16, 24) = 384 CTAs, one wave
    attn_kernel<<<g2, 128, ATT_SMEM>>>();

    // 3) Output projection
    dim3 g3(PD / 128, M1 / 128);   // (6, 32)
    sgemm_kernel<1><<<g3, 256>>>(nullptr, Wo, bo, out, M1, PD, K1);
}